// round 13
// baseline (speedup 1.0000x reference)
#include <cuda_runtime.h>
#include <math.h>

#define N_PTS 32768
#define H     64
#define NBLK  128
#define TPB   128          // 4 warps; each thread owns 2 points
#define PTS_PER_BLK 256
#define NELEM (N_PTS*3)
#define MAX_STEPS 24
#define NWARP (TPB/32)

// ---------------- persistent device state (no allocation) ----------------
__device__ volatile int   g_count[MAX_STEPS];
__device__ volatile float g_partials[2][NBLK];

// ---------------- dopri5 tableau ------------------------------------------
__constant__ float cC[7] = { 0.0f, 0.2f, 0.3f, 0.8f, (float)(8.0/9.0), 1.0f, 1.0f };
__constant__ float cA[7][6] = {
    {0,0,0,0,0,0},
    {(float)(1.0/5.0),0,0,0,0,0},
    {(float)(3.0/40.0),(float)(9.0/40.0),0,0,0,0},
    {(float)(44.0/45.0),(float)(-56.0/15.0),(float)(32.0/9.0),0,0,0},
    {(float)(19372.0/6561.0),(float)(-25360.0/2187.0),(float)(64448.0/6561.0),(float)(-212.0/729.0),0,0},
    {(float)(9017.0/3168.0),(float)(-355.0/33.0),(float)(46732.0/5247.0),(float)(49.0/176.0),(float)(-5103.0/18656.0),0},
    {(float)(35.0/384.0),0.0f,(float)(500.0/1113.0),(float)(125.0/192.0),(float)(-2187.0/6784.0),(float)(11.0/84.0)},
};
__constant__ float cB[7] = {
    (float)(35.0/384.0), 0.0f, (float)(500.0/1113.0), (float)(125.0/192.0),
    (float)(-2187.0/6784.0), (float)(11.0/84.0), 0.0f
};
__constant__ float cE[7] = {
    (float)(35.0/384.0 - 5179.0/57600.0),
    0.0f,
    (float)(500.0/1113.0 - 7571.0/16695.0),
    (float)(125.0/192.0 - 393.0/640.0),
    (float)(-2187.0/6784.0 + 92097.0/339200.0),
    (float)(11.0/84.0 - 187.0/2100.0),
    (float)(-1.0/40.0)
};

// ---------------- packed f32x2 helpers (Blackwell FFMA2) ------------------
__device__ __forceinline__ unsigned long long ffma2(unsigned long long a,
                                                    unsigned long long b,
                                                    unsigned long long c)
{
    unsigned long long d;
    asm("fma.rn.f32x2 %0, %1, %2, %3;" : "=l"(d) : "l"(a), "l"(b), "l"(c));
    return d;
}
__device__ __forceinline__ unsigned long long splat2(float x)
{
    unsigned long long d;
    asm("mov.b64 %0, {%1, %1};" : "=l"(d) : "f"(x));
    return d;
}
__device__ __forceinline__ void unpack2(unsigned long long v, float& lo, float& hi)
{
    asm("mov.b64 {%0, %1}, %2;" : "=f"(lo), "=f"(hi) : "l"(v));
}

// ---------------- hardware tanh: single MUFU.TANH -------------------------
__device__ __forceinline__ float fast_tanh(float x)
{
    float y;
    asm("tanh.approx.f32 %0, %1;" : "=f"(y) : "f"(x));
    return y;
}

// ---------------- dual-point MLP eval, single pass ------------------------
// Two points share every weight load; full 32 packed acc pairs per point so
// layer 1 runs once. Shared term t*W1t.w + b1 computed once for both points.
__device__ __forceinline__ void mlp_eval2(
    const float4* __restrict__ sW1t, const float* __restrict__ sb1,
    const float*  __restrict__ sW2,  const float* __restrict__ sb2,
    const float4* __restrict__ sW3,  const float* __restrict__ sb3,
    float t,
    float xA0, float xA1, float xA2,
    float xB0, float xB1, float xB2,
    float3& fA, float3& fB)
{
    unsigned long long accA[H / 2], accB[H / 2];   // 32 pairs = 64 neurons
    {
        const unsigned long long* b2p = (const unsigned long long*)sb2;
#pragma unroll
        for (int p = 0; p < H / 2; p++) { accA[p] = b2p[p]; accB[p] = b2p[p]; }
    }

#pragma unroll 4
    for (int k = 0; k < H; k++) {
        float4 w = sW1t[k];                        // broadcast LDS
        float tw = fmaf(t, w.w, sb1[k]);           // shared by A and B
        float aA = tw;
        aA = fmaf(xA2, w.z, aA);
        aA = fmaf(xA1, w.y, aA);
        aA = fmaf(xA0, w.x, aA);
        float aB = tw;
        aB = fmaf(xB2, w.z, aB);
        aB = fmaf(xB1, w.y, aB);
        aB = fmaf(xB0, w.x, aB);
        unsigned long long hsA = splat2(fast_tanh(aA));
        unsigned long long hsB = splat2(fast_tanh(aB));

        const ulonglong2* wrow = (const ulonglong2*)(sW2 + k * H);
#pragma unroll
        for (int q = 0; q < H / 4; q++) {          // 16 x 16B = full row
            ulonglong2 wv = wrow[q];               // broadcast LDS
            accA[2 * q]     = ffma2(hsA, wv.x, accA[2 * q]);
            accB[2 * q]     = ffma2(hsB, wv.x, accB[2 * q]);
            accA[2 * q + 1] = ffma2(hsA, wv.y, accA[2 * q + 1]);
            accB[2 * q + 1] = ffma2(hsB, wv.y, accB[2 * q + 1]);
        }
    }

    float oA0 = sb3[0], oA1 = sb3[1], oA2 = sb3[2];
    float oB0 = sb3[0], oB1 = sb3[1], oB2 = sb3[2];
#pragma unroll
    for (int p = 0; p < H / 2; p++) {
        float4 wa = sW3[2 * p];                    // broadcast
        float4 wb = sW3[2 * p + 1];
        float u, v;
        unpack2(accA[p], u, v);
        float ha = fast_tanh(u), hb = fast_tanh(v);
        oA0 = fmaf(ha, wa.x, oA0); oA1 = fmaf(ha, wa.y, oA1); oA2 = fmaf(ha, wa.z, oA2);
        oA0 = fmaf(hb, wb.x, oA0); oA1 = fmaf(hb, wb.y, oA1); oA2 = fmaf(hb, wb.z, oA2);
        unpack2(accB[p], u, v);
        ha = fast_tanh(u); hb = fast_tanh(v);
        oB0 = fmaf(ha, wa.x, oB0); oB1 = fmaf(ha, wa.y, oB1); oB2 = fmaf(ha, wa.z, oB2);
        oB0 = fmaf(hb, wb.x, oB0); oB1 = fmaf(hb, wb.y, oB1); oB2 = fmaf(hb, wb.z, oB2);
    }
    fA = make_float3(oA0, oA1, oA2);
    fB = make_float3(oB0, oB1, oB2);
}

// ---------------- init: reset barrier counters every replay ---------------
__global__ void ode_init_kernel()
{
    int i = threadIdx.x;
    if (i < MAX_STEPS) g_count[i] = 0;
}

// ---------------- persistent fused integrator (FSAL, 2 pts/thread) --------
__global__ void __launch_bounds__(TPB, 1)
ode_persistent_kernel(const float* __restrict__ yin,
                      const float* __restrict__ W1, const float* __restrict__ b1,
                      const float* __restrict__ W2, const float* __restrict__ b2,
                      const float* __restrict__ W3, const float* __restrict__ b3,
                      float* __restrict__ yout)
{
    __shared__ __align__(16) float4 sW1t[H];
    __shared__ __align__(16) float  sb1[H];
    __shared__ __align__(16) float  sW2[H * H];    // natural [k][j] layout
    __shared__ __align__(16) float  sb2[H];
    __shared__ __align__(16) float4 sW3[H];
    __shared__ __align__(16) float  sb3[4];
    __shared__ float  rwarp[NWARP];
    __shared__ float  rctrl[4];

    const int tid  = threadIdx.x;
    const int bid  = blockIdx.x;
    const int lane = tid & 31;
    const int wid  = tid >> 5;

    {
        const float4* src = (const float4*)W2;
        float4* dst = (float4*)sW2;
        for (int idx = tid; idx < H * H / 4; idx += TPB) dst[idx] = src[idx];
    }
    if (tid < H) {
        sW1t[tid] = make_float4(W1[0*H + tid], W1[1*H + tid], W1[2*H + tid], W1[3*H + tid]);
        sb1[tid] = b1[tid];
        sb2[tid] = b2[tid];
        sW3[tid] = make_float4(W3[tid*3 + 0], W3[tid*3 + 1], W3[tid*3 + 2], 0.0f);
    }
    if (tid < 3) sb3[tid] = b3[tid];
    __syncthreads();

    const int nA = bid * PTS_PER_BLK + tid;
    const int nB = nA + TPB;

    float yA0 = yin[3*nA + 0], yA1 = yin[3*nA + 1], yA2 = yin[3*nA + 2];
    float yB0 = yin[3*nB + 0], yB1 = yin[3*nB + 1], yB2 = yin[3*nB + 2];

    float t  = 0.0f;
    float dt = 0.05f;

    float kA0 = 0.0f, kA1 = 0.0f, kA2 = 0.0f;
    float kB0 = 0.0f, kB1 = 0.0f, kB2 = 0.0f;
    bool  have_k1 = false;

    for (int s = 0; s < MAX_STEPS; s++) {
        const float rem = 1.0f - t;
        if (!(rem > 1e-9f)) break;                 // identical across blocks
        const float dtc = fminf(dt, rem);

        float kbA[7][3], kbB[7][3];
#pragma unroll 1
        for (int i = 0; i < 7; i++) {
            if (i == 0 && have_k1) {
                kbA[0][0] = kA0; kbA[0][1] = kA1; kbA[0][2] = kA2;
                kbB[0][0] = kB0; kbB[0][1] = kB1; kbB[0][2] = kB2;
                continue;
            }
            float yiA0 = yA0, yiA1 = yA1, yiA2 = yA2;
            float yiB0 = yB0, yiB1 = yB1, yiB2 = yB2;
            for (int j = 0; j < i; j++) {
                float c = dtc * cA[i][j];
                yiA0 += c * kbA[j][0]; yiA1 += c * kbA[j][1]; yiA2 += c * kbA[j][2];
                yiB0 += c * kbB[j][0]; yiB1 += c * kbB[j][1]; yiB2 += c * kbB[j][2];
            }
            float3 fA, fB;
            mlp_eval2(sW1t, sb1, sW2, sb2, sW3, sb3, t + cC[i] * dtc,
                      yiA0, yiA1, yiA2, yiB0, yiB1, yiB2, fA, fB);
            kbA[i][0] = fA.x; kbA[i][1] = fA.y; kbA[i][2] = fA.z;
            kbB[i][0] = fB.x; kbB[i][1] = fB.y; kbB[i][2] = fB.z;
        }

        float ynA0 = yA0, ynA1 = yA1, ynA2 = yA2;
        float ynB0 = yB0, ynB1 = yB1, ynB2 = yB2;
        float yeA0 = 0.0f, yeA1 = 0.0f, yeA2 = 0.0f;
        float yeB0 = 0.0f, yeB1 = 0.0f, yeB2 = 0.0f;
        for (int i = 0; i < 7; i++) {
            float cb = dtc * cB[i];
            float ce = dtc * cE[i];
            ynA0 += cb * kbA[i][0]; ynA1 += cb * kbA[i][1]; ynA2 += cb * kbA[i][2];
            ynB0 += cb * kbB[i][0]; ynB1 += cb * kbB[i][1]; ynB2 += cb * kbB[i][2];
            yeA0 += ce * kbA[i][0]; yeA1 += ce * kbA[i][1]; yeA2 += ce * kbA[i][2];
            yeB0 += ce * kbB[i][0]; yeB1 += ce * kbB[i][1]; yeB2 += ce * kbB[i][2];
        }

        // ---- per-thread error (both points), warp reduce + cross-warp ----
        float local;
        {
            float tolA0 = 1e-5f + 1e-5f * fmaxf(fabsf(yA0), fabsf(ynA0));
            float tolA1 = 1e-5f + 1e-5f * fmaxf(fabsf(yA1), fabsf(ynA1));
            float tolA2 = 1e-5f + 1e-5f * fmaxf(fabsf(yA2), fabsf(ynA2));
            float tolB0 = 1e-5f + 1e-5f * fmaxf(fabsf(yB0), fabsf(ynB0));
            float tolB1 = 1e-5f + 1e-5f * fmaxf(fabsf(yB1), fabsf(ynB1));
            float tolB2 = 1e-5f + 1e-5f * fmaxf(fabsf(yB2), fabsf(ynB2));
            float rA0 = yeA0 / tolA0, rA1 = yeA1 / tolA1, rA2 = yeA2 / tolA2;
            float rB0 = yeB0 / tolB0, rB1 = yeB1 / tolB1, rB2 = yeB2 / tolB2;
            local = (rA0*rA0 + (rA1*rA1 + rA2*rA2))
                  + (rB0*rB0 + (rB1*rB1 + rB2*rB2));
        }
#pragma unroll
        for (int o = 16; o > 0; o >>= 1)
            local += __shfl_down_sync(0xFFFFFFFFu, local, o);
        if (lane == 0) rwarp[wid] = local;
        __syncthreads();

        // ---- grid barrier ----
        const int buf = s & 1;
        if (tid == 0) {
            float bsum = rwarp[0];
#pragma unroll
            for (int w = 1; w < NWARP; w++) bsum += rwarp[w];
            g_partials[buf][bid] = bsum;
            __threadfence();
            atomicAdd((int*)&g_count[s], 1);
            while (g_count[s] < NBLK) { }
            __threadfence();
        }
        __syncthreads();

        // ---- redundant deterministic controller ----
        if (wid < 4) {
            float v = g_partials[buf][wid * 32 + lane];
#pragma unroll
            for (int o = 16; o > 0; o >>= 1)
                v += __shfl_down_sync(0xFFFFFFFFu, v, o);
            if (lane == 0) rctrl[wid] = v;
        }
        __syncthreads();
        float total = ((rctrl[0] + rctrl[1]) + (rctrl[2] + rctrl[3]));
        __syncthreads();

        float err = sqrtf(total / (float)NELEM);
        err = fmaxf(err, 1e-10f);
        bool accept = err <= 1.0f;
        float factor = 0.9f * powf(err, -0.2f);
        factor = fminf(fmaxf(factor, 0.2f), 10.0f);
        if (accept) {
            t += dtc;
            yA0 = ynA0; yA1 = ynA1; yA2 = ynA2;
            yB0 = ynB0; yB1 = ynB1; yB2 = ynB2;
            kA0 = kbA[6][0]; kA1 = kbA[6][1]; kA2 = kbA[6][2];
            kB0 = kbB[6][0]; kB1 = kbB[6][1]; kB2 = kbB[6][2];
        } else {
            kA0 = kbA[0][0]; kA1 = kbA[0][1]; kA2 = kbA[0][2];
            kB0 = kbB[0][0]; kB1 = kbB[0][1]; kB2 = kbB[0][2];
        }
        have_k1 = true;
        dt = dtc * factor;
    }

    yout[3*nA + 0] = yA0; yout[3*nA + 1] = yA1; yout[3*nA + 2] = yA2;
    yout[3*nB + 0] = yB0; yout[3*nB + 1] = yB1; yout[3*nB + 2] = yB2;
}

// ---------------- launch --------------------------------------------------
extern "C" void kernel_launch(void* const* d_in, const int* in_sizes, int n_in,
                              void* d_out, int out_size)
{
    const float* y_in = (const float*)d_in[0];
    const float* W1   = (const float*)d_in[1];
    const float* b1   = (const float*)d_in[2];
    const float* W2   = (const float*)d_in[3];
    const float* b2   = (const float*)d_in[4];
    const float* W3   = (const float*)d_in[5];
    const float* b3   = (const float*)d_in[6];
    float* y = (float*)d_out;

    ode_init_kernel<<<1, 32>>>();
    ode_persistent_kernel<<<NBLK, TPB>>>(y_in, W1, b1, W2, b2, W3, b3, y);
}

// round 14
// speedup vs baseline: 1.2059x; 1.2059x over previous
#include <cuda_runtime.h>
#include <math.h>

#define N_PTS 32768
#define H     64
#define NBLK  128
#define TPB   128          // 4 warps; each thread owns 2 points
#define PTS_PER_BLK 256
#define NELEM (N_PTS*3)
#define MAX_STEPS 24
#define NWARP (TPB/32)

// ---------------- persistent device state (no allocation) ----------------
__device__ volatile int   g_count[MAX_STEPS];
__device__ volatile float g_partials[2][NBLK];

// ---------------- dopri5 tableau ------------------------------------------
__constant__ float cC[7] = { 0.0f, 0.2f, 0.3f, 0.8f, (float)(8.0/9.0), 1.0f, 1.0f };
__constant__ float cA[7][6] = {
    {0,0,0,0,0,0},
    {(float)(1.0/5.0),0,0,0,0,0},
    {(float)(3.0/40.0),(float)(9.0/40.0),0,0,0,0},
    {(float)(44.0/45.0),(float)(-56.0/15.0),(float)(32.0/9.0),0,0,0},
    {(float)(19372.0/6561.0),(float)(-25360.0/2187.0),(float)(64448.0/6561.0),(float)(-212.0/729.0),0,0},
    {(float)(9017.0/3168.0),(float)(-355.0/33.0),(float)(46732.0/5247.0),(float)(49.0/176.0),(float)(-5103.0/18656.0),0},
    {(float)(35.0/384.0),0.0f,(float)(500.0/1113.0),(float)(125.0/192.0),(float)(-2187.0/6784.0),(float)(11.0/84.0)},
};
__constant__ float cB[7] = {
    (float)(35.0/384.0), 0.0f, (float)(500.0/1113.0), (float)(125.0/192.0),
    (float)(-2187.0/6784.0), (float)(11.0/84.0), 0.0f
};
__constant__ float cE[7] = {
    (float)(35.0/384.0 - 5179.0/57600.0),
    0.0f,
    (float)(500.0/1113.0 - 7571.0/16695.0),
    (float)(125.0/192.0 - 393.0/640.0),
    (float)(-2187.0/6784.0 + 92097.0/339200.0),
    (float)(11.0/84.0 - 187.0/2100.0),
    (float)(-1.0/40.0)
};

// ---------------- packed f32x2 helpers (Blackwell FFMA2) ------------------
__device__ __forceinline__ unsigned long long ffma2(unsigned long long a,
                                                    unsigned long long b,
                                                    unsigned long long c)
{
    unsigned long long d;
    asm("fma.rn.f32x2 %0, %1, %2, %3;" : "=l"(d) : "l"(a), "l"(b), "l"(c));
    return d;
}
__device__ __forceinline__ unsigned long long splat2(float x)
{
    unsigned long long d;
    asm("mov.b64 %0, {%1, %1};" : "=l"(d) : "f"(x));
    return d;
}
__device__ __forceinline__ void unpack2(unsigned long long v, float& lo, float& hi)
{
    asm("mov.b64 {%0, %1}, %2;" : "=f"(lo), "=f"(hi) : "l"(v));
}

// ---------------- hardware tanh: single MUFU.TANH -------------------------
__device__ __forceinline__ float fast_tanh(float x)
{
    float y;
    asm("tanh.approx.f32 %0, %1;" : "=f"(y) : "f"(x));
    return y;
}

// ---------------- dual-point MLP eval, single pass ------------------------
// Two points share every weight load; full 32 packed acc pairs per point.
// Unroll kept at 2 to bound the live weight-register window (R13 lesson).
__device__ __forceinline__ void mlp_eval2(
    const float4* __restrict__ sW1t, const float* __restrict__ sb1,
    const float*  __restrict__ sW2,  const float* __restrict__ sb2,
    const float4* __restrict__ sW3,  const float* __restrict__ sb3,
    float t,
    float xA0, float xA1, float xA2,
    float xB0, float xB1, float xB2,
    float3& fA, float3& fB)
{
    unsigned long long accA[H / 2], accB[H / 2];   // 32 pairs = 64 neurons
    {
        const unsigned long long* b2p = (const unsigned long long*)sb2;
#pragma unroll
        for (int p = 0; p < H / 2; p++) { accA[p] = b2p[p]; accB[p] = b2p[p]; }
    }

#pragma unroll 2
    for (int k = 0; k < H; k++) {
        float4 w = sW1t[k];                        // broadcast LDS
        float tw = fmaf(t, w.w, sb1[k]);           // shared by A and B
        float aA = tw;
        aA = fmaf(xA2, w.z, aA);
        aA = fmaf(xA1, w.y, aA);
        aA = fmaf(xA0, w.x, aA);
        float aB = tw;
        aB = fmaf(xB2, w.z, aB);
        aB = fmaf(xB1, w.y, aB);
        aB = fmaf(xB0, w.x, aB);
        unsigned long long hsA = splat2(fast_tanh(aA));
        unsigned long long hsB = splat2(fast_tanh(aB));

        const ulonglong2* wrow = (const ulonglong2*)(sW2 + k * H);
#pragma unroll
        for (int q = 0; q < H / 4; q++) {          // 16 x 16B = full row
            ulonglong2 wv = wrow[q];               // broadcast LDS
            accA[2 * q]     = ffma2(hsA, wv.x, accA[2 * q]);
            accB[2 * q]     = ffma2(hsB, wv.x, accB[2 * q]);
            accA[2 * q + 1] = ffma2(hsA, wv.y, accA[2 * q + 1]);
            accB[2 * q + 1] = ffma2(hsB, wv.y, accB[2 * q + 1]);
        }
    }

    float oA0 = sb3[0], oA1 = sb3[1], oA2 = sb3[2];
    float oB0 = sb3[0], oB1 = sb3[1], oB2 = sb3[2];
#pragma unroll
    for (int p = 0; p < H / 2; p++) {
        float4 wa = sW3[2 * p];                    // broadcast
        float4 wb = sW3[2 * p + 1];
        float u, v;
        unpack2(accA[p], u, v);
        float ha = fast_tanh(u), hb = fast_tanh(v);
        oA0 = fmaf(ha, wa.x, oA0); oA1 = fmaf(ha, wa.y, oA1); oA2 = fmaf(ha, wa.z, oA2);
        oA0 = fmaf(hb, wb.x, oA0); oA1 = fmaf(hb, wb.y, oA1); oA2 = fmaf(hb, wb.z, oA2);
        unpack2(accB[p], u, v);
        ha = fast_tanh(u); hb = fast_tanh(v);
        oB0 = fmaf(ha, wa.x, oB0); oB1 = fmaf(ha, wa.y, oB1); oB2 = fmaf(ha, wa.z, oB2);
        oB0 = fmaf(hb, wb.x, oB0); oB1 = fmaf(hb, wb.y, oB1); oB2 = fmaf(hb, wb.z, oB2);
    }
    fA = make_float3(oA0, oA1, oA2);
    fB = make_float3(oB0, oB1, oB2);
}

// ---------------- init: reset barrier counters every replay ---------------
__global__ void ode_init_kernel()
{
    int i = threadIdx.x;
    if (i < MAX_STEPS) g_count[i] = 0;
}

// ---------------- persistent fused integrator (FSAL, kb in smem) ----------
__global__ void __launch_bounds__(TPB, 1)
ode_persistent_kernel(const float* __restrict__ yin,
                      const float* __restrict__ W1, const float* __restrict__ b1,
                      const float* __restrict__ W2, const float* __restrict__ b2,
                      const float* __restrict__ W3, const float* __restrict__ b3,
                      float* __restrict__ yout)
{
    __shared__ __align__(16) float4 sW1t[H];
    __shared__ __align__(16) float  sb1[H];
    __shared__ __align__(16) float  sW2[H * H];    // natural [k][j] layout
    __shared__ __align__(16) float  sb2[H];
    __shared__ __align__(16) float4 sW3[H];
    __shared__ __align__(16) float  sb3[4];
    __shared__ float  kbs[21 * 2 * TPB];           // stage storage [c][pt][tid]
    __shared__ float  rwarp[NWARP];
    __shared__ float  rctrl[4];

    const int tid  = threadIdx.x;
    const int bid  = blockIdx.x;
    const int lane = tid & 31;
    const int wid  = tid >> 5;

    // thread-private smem slot accessor: component c in [0,21), pt in {0,1}
#define KBS(c, pt) kbs[(((c) << 1) | (pt)) * TPB + tid]

    {
        const float4* src = (const float4*)W2;
        float4* dst = (float4*)sW2;
        for (int idx = tid; idx < H * H / 4; idx += TPB) dst[idx] = src[idx];
    }
    if (tid < H) {
        sW1t[tid] = make_float4(W1[0*H + tid], W1[1*H + tid], W1[2*H + tid], W1[3*H + tid]);
        sb1[tid] = b1[tid];
        sb2[tid] = b2[tid];
        sW3[tid] = make_float4(W3[tid*3 + 0], W3[tid*3 + 1], W3[tid*3 + 2], 0.0f);
    }
    if (tid < 3) sb3[tid] = b3[tid];
    __syncthreads();

    const int nA = bid * PTS_PER_BLK + tid;
    const int nB = nA + TPB;

    float yA0 = yin[3*nA + 0], yA1 = yin[3*nA + 1], yA2 = yin[3*nA + 2];
    float yB0 = yin[3*nB + 0], yB1 = yin[3*nB + 1], yB2 = yin[3*nB + 2];

    float t  = 0.0f;
    float dt = 0.05f;
    bool  have_k1 = false;   // when true, KBS slot 0 holds valid k1 at (t, y)

    for (int s = 0; s < MAX_STEPS; s++) {
        const float rem = 1.0f - t;
        if (!(rem > 1e-9f)) break;                 // identical across blocks
        const float dtc = fminf(dt, rem);

        // ---- 7 dopri5 stages; stage results live in thread-private smem ----
#pragma unroll 1
        for (int i = 0; i < 7; i++) {
            if (i == 0 && have_k1) continue;       // slot 0 already valid (FSAL)
            float yiA0 = yA0, yiA1 = yA1, yiA2 = yA2;
            float yiB0 = yB0, yiB1 = yB1, yiB2 = yB2;
            for (int j = 0; j < i; j++) {
                float c = dtc * cA[i][j];
                yiA0 += c * KBS(j*3 + 0, 0); yiA1 += c * KBS(j*3 + 1, 0); yiA2 += c * KBS(j*3 + 2, 0);
                yiB0 += c * KBS(j*3 + 0, 1); yiB1 += c * KBS(j*3 + 1, 1); yiB2 += c * KBS(j*3 + 2, 1);
            }
            float3 fA, fB;
            mlp_eval2(sW1t, sb1, sW2, sb2, sW3, sb3, t + cC[i] * dtc,
                      yiA0, yiA1, yiA2, yiB0, yiB1, yiB2, fA, fB);
            KBS(i*3 + 0, 0) = fA.x; KBS(i*3 + 1, 0) = fA.y; KBS(i*3 + 2, 0) = fA.z;
            KBS(i*3 + 0, 1) = fB.x; KBS(i*3 + 1, 1) = fB.y; KBS(i*3 + 2, 1) = fB.z;
        }

        float ynA0 = yA0, ynA1 = yA1, ynA2 = yA2;
        float ynB0 = yB0, ynB1 = yB1, ynB2 = yB2;
        float yeA0 = 0.0f, yeA1 = 0.0f, yeA2 = 0.0f;
        float yeB0 = 0.0f, yeB1 = 0.0f, yeB2 = 0.0f;
        for (int i = 0; i < 7; i++) {
            float cb = dtc * cB[i];
            float ce = dtc * cE[i];
            float vA0 = KBS(i*3 + 0, 0), vA1 = KBS(i*3 + 1, 0), vA2 = KBS(i*3 + 2, 0);
            float vB0 = KBS(i*3 + 0, 1), vB1 = KBS(i*3 + 1, 1), vB2 = KBS(i*3 + 2, 1);
            ynA0 += cb * vA0; ynA1 += cb * vA1; ynA2 += cb * vA2;
            ynB0 += cb * vB0; ynB1 += cb * vB1; ynB2 += cb * vB2;
            yeA0 += ce * vA0; yeA1 += ce * vA1; yeA2 += ce * vA2;
            yeB0 += ce * vB0; yeB1 += ce * vB1; yeB2 += ce * vB2;
        }

        // ---- per-thread error (both points), warp reduce + cross-warp ----
        float local;
        {
            float tolA0 = 1e-5f + 1e-5f * fmaxf(fabsf(yA0), fabsf(ynA0));
            float tolA1 = 1e-5f + 1e-5f * fmaxf(fabsf(yA1), fabsf(ynA1));
            float tolA2 = 1e-5f + 1e-5f * fmaxf(fabsf(yA2), fabsf(ynA2));
            float tolB0 = 1e-5f + 1e-5f * fmaxf(fabsf(yB0), fabsf(ynB0));
            float tolB1 = 1e-5f + 1e-5f * fmaxf(fabsf(yB1), fabsf(ynB1));
            float tolB2 = 1e-5f + 1e-5f * fmaxf(fabsf(yB2), fabsf(ynB2));
            float rA0 = yeA0 / tolA0, rA1 = yeA1 / tolA1, rA2 = yeA2 / tolA2;
            float rB0 = yeB0 / tolB0, rB1 = yeB1 / tolB1, rB2 = yeB2 / tolB2;
            local = (rA0*rA0 + (rA1*rA1 + rA2*rA2))
                  + (rB0*rB0 + (rB1*rB1 + rB2*rB2));
        }
#pragma unroll
        for (int o = 16; o > 0; o >>= 1)
            local += __shfl_down_sync(0xFFFFFFFFu, local, o);
        if (lane == 0) rwarp[wid] = local;
        __syncthreads();

        // ---- grid barrier ----
        const int buf = s & 1;
        if (tid == 0) {
            float bsum = rwarp[0];
#pragma unroll
            for (int w = 1; w < NWARP; w++) bsum += rwarp[w];
            g_partials[buf][bid] = bsum;
            __threadfence();
            atomicAdd((int*)&g_count[s], 1);
            while (g_count[s] < NBLK) { }
            __threadfence();
        }
        __syncthreads();

        // ---- redundant deterministic controller ----
        if (wid < 4) {
            float v = g_partials[buf][wid * 32 + lane];
#pragma unroll
            for (int o = 16; o > 0; o >>= 1)
                v += __shfl_down_sync(0xFFFFFFFFu, v, o);
            if (lane == 0) rctrl[wid] = v;
        }
        __syncthreads();
        float total = ((rctrl[0] + rctrl[1]) + (rctrl[2] + rctrl[3]));
        __syncthreads();

        float err = sqrtf(total / (float)NELEM);
        err = fmaxf(err, 1e-10f);
        bool accept = err <= 1.0f;
        float factor = 0.9f * powf(err, -0.2f);
        factor = fminf(fmaxf(factor, 0.2f), 10.0f);
        if (accept) {
            t += dtc;
            yA0 = ynA0; yA1 = ynA1; yA2 = ynA2;
            yB0 = ynB0; yB1 = ynB1; yB2 = ynB2;
            // FSAL: stage-6 result is k1 at (t_new, y_new) -> move to slot 0
#pragma unroll
            for (int c = 0; c < 3; c++) {
                KBS(c, 0) = KBS(18 + c, 0);
                KBS(c, 1) = KBS(18 + c, 1);
            }
        }
        // on reject: slot 0 already holds k1 at unchanged (t, y)
        have_k1 = true;
        dt = dtc * factor;
    }

    yout[3*nA + 0] = yA0; yout[3*nA + 1] = yA1; yout[3*nA + 2] = yA2;
    yout[3*nB + 0] = yB0; yout[3*nB + 1] = yB1; yout[3*nB + 2] = yB2;
#undef KBS
}

// ---------------- launch --------------------------------------------------
extern "C" void kernel_launch(void* const* d_in, const int* in_sizes, int n_in,
                              void* d_out, int out_size)
{
    const float* y_in = (const float*)d_in[0];
    const float* W1   = (const float*)d_in[1];
    const float* b1   = (const float*)d_in[2];
    const float* W2   = (const float*)d_in[3];
    const float* b2   = (const float*)d_in[4];
    const float* W3   = (const float*)d_in[5];
    const float* b3   = (const float*)d_in[6];
    float* y = (float*)d_out;

    ode_init_kernel<<<1, 32>>>();
    ode_persistent_kernel<<<NBLK, TPB>>>(y_in, W1, b1, W2, b2, W3, b3, y);
}

// round 15
// speedup vs baseline: 2.4372x; 2.0210x over previous
#include <cuda_runtime.h>
#include <math.h>

#define N_PTS 32768
#define H     64
#define NBLK  128
#define TPB   128          // 4 warps; each thread owns 2 points
#define PTS_PER_BLK 256
#define NELEM (N_PTS*3)
#define MAX_STEPS 24
#define NWARP (TPB/32)

// ---- dynamic smem layout (bytes) ----
#define SM_W2     0                         // float[4096]   16384 B
#define SM_W1T    16384                     // float4[64]     1024 B
#define SM_B1     17408                     // float[64]       256 B
#define SM_B2     17664                     // float[64]       256 B
#define SM_W3     17920                     // float4[64]     1024 B
#define SM_B3     18944                     // float[4]         16 B (pad to 64)
#define SM_HC     19008                     // ull[64*TPB]   65536 B
#define SM_RW     (19008 + 65536)           // float[NWARP]
#define SM_RC     (SM_RW + 4*NWARP)         // float[4]
#define SMEM_TOTAL (SM_RC + 16)

// ---------------- persistent device state (no allocation) ----------------
__device__ volatile int   g_count[MAX_STEPS];
__device__ volatile float g_partials[2][NBLK];

// ---------------- dopri5 tableau ------------------------------------------
__constant__ float cC[7] = { 0.0f, 0.2f, 0.3f, 0.8f, (float)(8.0/9.0), 1.0f, 1.0f };
__constant__ float cA[7][6] = {
    {0,0,0,0,0,0},
    {(float)(1.0/5.0),0,0,0,0,0},
    {(float)(3.0/40.0),(float)(9.0/40.0),0,0,0,0},
    {(float)(44.0/45.0),(float)(-56.0/15.0),(float)(32.0/9.0),0,0,0},
    {(float)(19372.0/6561.0),(float)(-25360.0/2187.0),(float)(64448.0/6561.0),(float)(-212.0/729.0),0,0},
    {(float)(9017.0/3168.0),(float)(-355.0/33.0),(float)(46732.0/5247.0),(float)(49.0/176.0),(float)(-5103.0/18656.0),0},
    {(float)(35.0/384.0),0.0f,(float)(500.0/1113.0),(float)(125.0/192.0),(float)(-2187.0/6784.0),(float)(11.0/84.0)},
};
__constant__ float cB[7] = {
    (float)(35.0/384.0), 0.0f, (float)(500.0/1113.0), (float)(125.0/192.0),
    (float)(-2187.0/6784.0), (float)(11.0/84.0), 0.0f
};
__constant__ float cE[7] = {
    (float)(35.0/384.0 - 5179.0/57600.0),
    0.0f,
    (float)(500.0/1113.0 - 7571.0/16695.0),
    (float)(125.0/192.0 - 393.0/640.0),
    (float)(-2187.0/6784.0 + 92097.0/339200.0),
    (float)(11.0/84.0 - 187.0/2100.0),
    (float)(-1.0/40.0)
};

// ---------------- packed f32x2 helpers (Blackwell FFMA2) ------------------
__device__ __forceinline__ unsigned long long ffma2(unsigned long long a,
                                                    unsigned long long b,
                                                    unsigned long long c)
{
    unsigned long long d;
    asm("fma.rn.f32x2 %0, %1, %2, %3;" : "=l"(d) : "l"(a), "l"(b), "l"(c));
    return d;
}
__device__ __forceinline__ unsigned long long splat2(float x)
{
    unsigned long long d;
    asm("mov.b64 %0, {%1, %1};" : "=l"(d) : "f"(x));
    return d;
}
__device__ __forceinline__ unsigned long long pack2(float lo, float hi)
{
    unsigned long long d;
    asm("mov.b64 %0, {%1, %2};" : "=l"(d) : "f"(lo), "f"(hi));
    return d;
}
__device__ __forceinline__ void unpack2(unsigned long long v, float& lo, float& hi)
{
    asm("mov.b64 {%0, %1}, %2;" : "=f"(lo), "=f"(hi) : "l"(v));
}

// ---------------- hardware tanh: single MUFU.TANH -------------------------
__device__ __forceinline__ float fast_tanh(float x)
{
    float y;
    asm("tanh.approx.f32 %0, %1;" : "=f"(y) : "f"(x));
    return y;
}

// ---------------- dual-point MLP eval: 2 passes, h cached -----------------
// Pass 0 (neurons 0..31): compute layer-1 h on the fly, cache packed (hA,hB)
// in thread-private smem. Pass 1 (neurons 32..63): reload h from cache.
// Identical arithmetic order to the R12 two-pass version -> bitwise equal.
__device__ __forceinline__ void mlp_eval2(
    const float4* __restrict__ sW1t, const float* __restrict__ sb1,
    const float*  __restrict__ sW2,  const float* __restrict__ sb2,
    const float4* __restrict__ sW3,  const float* __restrict__ sb3,
    unsigned long long* __restrict__ hc,   // thread-private column, stride TPB
    float t,
    float xA0, float xA1, float xA2,
    float xB0, float xB1, float xB2,
    float3& fA, float3& fB)
{
    float oA0 = sb3[0], oA1 = sb3[1], oA2 = sb3[2];
    float oB0 = sb3[0], oB1 = sb3[1], oB2 = sb3[2];

    // ---- pass 0: neurons [0,32), compute + cache h ----
    {
        unsigned long long accA[H / 4], accB[H / 4];
        {
            const unsigned long long* b2p = (const unsigned long long*)sb2;
#pragma unroll
            for (int p = 0; p < H / 4; p++) { accA[p] = b2p[p]; accB[p] = b2p[p]; }
        }
#pragma unroll 4
        for (int k = 0; k < H; k++) {
            float4 w = sW1t[k];                    // broadcast LDS
            float tw = fmaf(t, w.w, sb1[k]);
            float aA = tw;
            aA = fmaf(xA2, w.z, aA);
            aA = fmaf(xA1, w.y, aA);
            aA = fmaf(xA0, w.x, aA);
            float aB = tw;
            aB = fmaf(xB2, w.z, aB);
            aB = fmaf(xB1, w.y, aB);
            aB = fmaf(xB0, w.x, aB);
            float hA = fast_tanh(aA);
            float hB = fast_tanh(aB);
            hc[k * TPB] = pack2(hA, hB);           // STS.64, conflict-free
            unsigned long long hsA = splat2(hA);
            unsigned long long hsB = splat2(hB);

            const ulonglong2* wrow = (const ulonglong2*)(sW2 + k * H);
#pragma unroll
            for (int q = 0; q < H / 8; q++) {      // 8 x 16B = neurons 0..31
                ulonglong2 wv = wrow[q];
                accA[2 * q]     = ffma2(hsA, wv.x, accA[2 * q]);
                accB[2 * q]     = ffma2(hsB, wv.x, accB[2 * q]);
                accA[2 * q + 1] = ffma2(hsA, wv.y, accA[2 * q + 1]);
                accB[2 * q + 1] = ffma2(hsB, wv.y, accB[2 * q + 1]);
            }
        }
#pragma unroll
        for (int p = 0; p < H / 4; p++) {
            float4 wa = sW3[2 * p];
            float4 wb = sW3[2 * p + 1];
            float u, v;
            unpack2(accA[p], u, v);
            float ha = fast_tanh(u), hbv = fast_tanh(v);
            oA0 = fmaf(ha, wa.x, oA0); oA1 = fmaf(ha, wa.y, oA1); oA2 = fmaf(ha, wa.z, oA2);
            oA0 = fmaf(hbv, wb.x, oA0); oA1 = fmaf(hbv, wb.y, oA1); oA2 = fmaf(hbv, wb.z, oA2);
            unpack2(accB[p], u, v);
            ha = fast_tanh(u); hbv = fast_tanh(v);
            oB0 = fmaf(ha, wa.x, oB0); oB1 = fmaf(ha, wa.y, oB1); oB2 = fmaf(ha, wa.z, oB2);
            oB0 = fmaf(hbv, wb.x, oB0); oB1 = fmaf(hbv, wb.y, oB1); oB2 = fmaf(hbv, wb.z, oB2);
        }
    }

    // ---- pass 1: neurons [32,64), h from cache ----
    {
        unsigned long long accA[H / 4], accB[H / 4];
        {
            const unsigned long long* b2p = (const unsigned long long*)(sb2 + H / 2);
#pragma unroll
            for (int p = 0; p < H / 4; p++) { accA[p] = b2p[p]; accB[p] = b2p[p]; }
        }
#pragma unroll 8
        for (int k = 0; k < H; k++) {
            float hA, hB;
            unpack2(hc[k * TPB], hA, hB);          // LDS.64, conflict-free
            unsigned long long hsA = splat2(hA);
            unsigned long long hsB = splat2(hB);

            const ulonglong2* wrow = (const ulonglong2*)(sW2 + k * H + H / 2);
#pragma unroll
            for (int q = 0; q < H / 8; q++) {      // neurons 32..63
                ulonglong2 wv = wrow[q];
                accA[2 * q]     = ffma2(hsA, wv.x, accA[2 * q]);
                accB[2 * q]     = ffma2(hsB, wv.x, accB[2 * q]);
                accA[2 * q + 1] = ffma2(hsA, wv.y, accA[2 * q + 1]);
                accB[2 * q + 1] = ffma2(hsB, wv.y, accB[2 * q + 1]);
            }
        }
#pragma unroll
        for (int p = 0; p < H / 4; p++) {
            float4 wa = sW3[H / 2 + 2 * p];
            float4 wb = sW3[H / 2 + 2 * p + 1];
            float u, v;
            unpack2(accA[p], u, v);
            float ha = fast_tanh(u), hbv = fast_tanh(v);
            oA0 = fmaf(ha, wa.x, oA0); oA1 = fmaf(ha, wa.y, oA1); oA2 = fmaf(ha, wa.z, oA2);
            oA0 = fmaf(hbv, wb.x, oA0); oA1 = fmaf(hbv, wb.y, oA1); oA2 = fmaf(hbv, wb.z, oA2);
            unpack2(accB[p], u, v);
            ha = fast_tanh(u); hbv = fast_tanh(v);
            oB0 = fmaf(ha, wa.x, oB0); oB1 = fmaf(ha, wa.y, oB1); oB2 = fmaf(ha, wa.z, oB2);
            oB0 = fmaf(hbv, wb.x, oB0); oB1 = fmaf(hbv, wb.y, oB1); oB2 = fmaf(hbv, wb.z, oB2);
        }
    }

    fA = make_float3(oA0, oA1, oA2);
    fB = make_float3(oB0, oB1, oB2);
}

// ---------------- init: reset barrier counters every replay ---------------
__global__ void ode_init_kernel()
{
    int i = threadIdx.x;
    if (i < MAX_STEPS) g_count[i] = 0;
}

// ---------------- persistent fused integrator (FSAL, 2 pts/thread) --------
__global__ void __launch_bounds__(TPB, 1)
ode_persistent_kernel(const float* __restrict__ yin,
                      const float* __restrict__ W1, const float* __restrict__ b1,
                      const float* __restrict__ W2, const float* __restrict__ b2,
                      const float* __restrict__ W3, const float* __restrict__ b3,
                      float* __restrict__ yout)
{
    extern __shared__ __align__(16) char smraw[];
    float*  sW2  = (float*)(smraw + SM_W2);
    float4* sW1t = (float4*)(smraw + SM_W1T);
    float*  sb1  = (float*)(smraw + SM_B1);
    float*  sb2  = (float*)(smraw + SM_B2);
    float4* sW3  = (float4*)(smraw + SM_W3);
    float*  sb3  = (float*)(smraw + SM_B3);
    unsigned long long* hcache = (unsigned long long*)(smraw + SM_HC);
    float*  rwarp = (float*)(smraw + SM_RW);
    float*  rctrl = (float*)(smraw + SM_RC);

    const int tid  = threadIdx.x;
    const int bid  = blockIdx.x;
    const int lane = tid & 31;
    const int wid  = tid >> 5;

    {
        const float4* src = (const float4*)W2;
        float4* dst = (float4*)sW2;
        for (int idx = tid; idx < H * H / 4; idx += TPB) dst[idx] = src[idx];
    }
    if (tid < H) {
        sW1t[tid] = make_float4(W1[0*H + tid], W1[1*H + tid], W1[2*H + tid], W1[3*H + tid]);
        sb1[tid] = b1[tid];
        sb2[tid] = b2[tid];
        sW3[tid] = make_float4(W3[tid*3 + 0], W3[tid*3 + 1], W3[tid*3 + 2], 0.0f);
    }
    if (tid < 3) sb3[tid] = b3[tid];
    __syncthreads();

    unsigned long long* hc = hcache + tid;   // thread-private column

    const int nA = bid * PTS_PER_BLK + tid;
    const int nB = nA + TPB;

    float yA0 = yin[3*nA + 0], yA1 = yin[3*nA + 1], yA2 = yin[3*nA + 2];
    float yB0 = yin[3*nB + 0], yB1 = yin[3*nB + 1], yB2 = yin[3*nB + 2];

    float t  = 0.0f;
    float dt = 0.05f;

    float kA0 = 0.0f, kA1 = 0.0f, kA2 = 0.0f;
    float kB0 = 0.0f, kB1 = 0.0f, kB2 = 0.0f;
    bool  have_k1 = false;

    for (int s = 0; s < MAX_STEPS; s++) {
        const float rem = 1.0f - t;
        if (!(rem > 1e-9f)) break;                 // identical across blocks
        const float dtc = fminf(dt, rem);

        float kbA[7][3], kbB[7][3];
#pragma unroll 1
        for (int i = 0; i < 7; i++) {
            if (i == 0 && have_k1) {
                kbA[0][0] = kA0; kbA[0][1] = kA1; kbA[0][2] = kA2;
                kbB[0][0] = kB0; kbB[0][1] = kB1; kbB[0][2] = kB2;
                continue;
            }
            float yiA0 = yA0, yiA1 = yA1, yiA2 = yA2;
            float yiB0 = yB0, yiB1 = yB1, yiB2 = yB2;
            for (int j = 0; j < i; j++) {
                float c = dtc * cA[i][j];
                yiA0 += c * kbA[j][0]; yiA1 += c * kbA[j][1]; yiA2 += c * kbA[j][2];
                yiB0 += c * kbB[j][0]; yiB1 += c * kbB[j][1]; yiB2 += c * kbB[j][2];
            }
            float3 fA, fB;
            mlp_eval2(sW1t, sb1, sW2, sb2, sW3, sb3, hc, t + cC[i] * dtc,
                      yiA0, yiA1, yiA2, yiB0, yiB1, yiB2, fA, fB);
            kbA[i][0] = fA.x; kbA[i][1] = fA.y; kbA[i][2] = fA.z;
            kbB[i][0] = fB.x; kbB[i][1] = fB.y; kbB[i][2] = fB.z;
        }

        float ynA0 = yA0, ynA1 = yA1, ynA2 = yA2;
        float ynB0 = yB0, ynB1 = yB1, ynB2 = yB2;
        float yeA0 = 0.0f, yeA1 = 0.0f, yeA2 = 0.0f;
        float yeB0 = 0.0f, yeB1 = 0.0f, yeB2 = 0.0f;
        for (int i = 0; i < 7; i++) {
            float cb = dtc * cB[i];
            float ce = dtc * cE[i];
            ynA0 += cb * kbA[i][0]; ynA1 += cb * kbA[i][1]; ynA2 += cb * kbA[i][2];
            ynB0 += cb * kbB[i][0]; ynB1 += cb * kbB[i][1]; ynB2 += cb * kbB[i][2];
            yeA0 += ce * kbA[i][0]; yeA1 += ce * kbA[i][1]; yeA2 += ce * kbA[i][2];
            yeB0 += ce * kbB[i][0]; yeB1 += ce * kbB[i][1]; yeB2 += ce * kbB[i][2];
        }

        // ---- per-thread error (both points), warp reduce + cross-warp ----
        float local;
        {
            float tolA0 = 1e-5f + 1e-5f * fmaxf(fabsf(yA0), fabsf(ynA0));
            float tolA1 = 1e-5f + 1e-5f * fmaxf(fabsf(yA1), fabsf(ynA1));
            float tolA2 = 1e-5f + 1e-5f * fmaxf(fabsf(yA2), fabsf(ynA2));
            float tolB0 = 1e-5f + 1e-5f * fmaxf(fabsf(yB0), fabsf(ynB0));
            float tolB1 = 1e-5f + 1e-5f * fmaxf(fabsf(yB1), fabsf(ynB1));
            float tolB2 = 1e-5f + 1e-5f * fmaxf(fabsf(yB2), fabsf(ynB2));
            float rA0 = yeA0 / tolA0, rA1 = yeA1 / tolA1, rA2 = yeA2 / tolA2;
            float rB0 = yeB0 / tolB0, rB1 = yeB1 / tolB1, rB2 = yeB2 / tolB2;
            local = (rA0*rA0 + (rA1*rA1 + rA2*rA2))
                  + (rB0*rB0 + (rB1*rB1 + rB2*rB2));
        }
#pragma unroll
        for (int o = 16; o > 0; o >>= 1)
            local += __shfl_down_sync(0xFFFFFFFFu, local, o);
        if (lane == 0) rwarp[wid] = local;
        __syncthreads();

        // ---- grid barrier ----
        const int buf = s & 1;
        if (tid == 0) {
            float bsum = rwarp[0];
#pragma unroll
            for (int w = 1; w < NWARP; w++) bsum += rwarp[w];
            g_partials[buf][bid] = bsum;
            __threadfence();
            atomicAdd((int*)&g_count[s], 1);
            while (g_count[s] < NBLK) { }
            __threadfence();
        }
        __syncthreads();

        // ---- redundant deterministic controller ----
        if (wid < 4) {
            float v = g_partials[buf][wid * 32 + lane];
#pragma unroll
            for (int o = 16; o > 0; o >>= 1)
                v += __shfl_down_sync(0xFFFFFFFFu, v, o);
            if (lane == 0) rctrl[wid] = v;
        }
        __syncthreads();
        float total = ((rctrl[0] + rctrl[1]) + (rctrl[2] + rctrl[3]));
        __syncthreads();

        float err = sqrtf(total / (float)NELEM);
        err = fmaxf(err, 1e-10f);
        bool accept = err <= 1.0f;
        float factor = 0.9f * powf(err, -0.2f);
        factor = fminf(fmaxf(factor, 0.2f), 10.0f);
        if (accept) {
            t += dtc;
            yA0 = ynA0; yA1 = ynA1; yA2 = ynA2;
            yB0 = ynB0; yB1 = ynB1; yB2 = ynB2;
            kA0 = kbA[6][0]; kA1 = kbA[6][1]; kA2 = kbA[6][2];
            kB0 = kbB[6][0]; kB1 = kbB[6][1]; kB2 = kbB[6][2];
        } else {
            kA0 = kbA[0][0]; kA1 = kbA[0][1]; kA2 = kbA[0][2];
            kB0 = kbB[0][0]; kB1 = kbB[0][1]; kB2 = kbB[0][2];
        }
        have_k1 = true;
        dt = dtc * factor;
    }

    yout[3*nA + 0] = yA0; yout[3*nA + 1] = yA1; yout[3*nA + 2] = yA2;
    yout[3*nB + 0] = yB0; yout[3*nB + 1] = yB1; yout[3*nB + 2] = yB2;
}

// ---------------- launch --------------------------------------------------
extern "C" void kernel_launch(void* const* d_in, const int* in_sizes, int n_in,
                              void* d_out, int out_size)
{
    const float* y_in = (const float*)d_in[0];
    const float* W1   = (const float*)d_in[1];
    const float* b1   = (const float*)d_in[2];
    const float* W2   = (const float*)d_in[3];
    const float* b2   = (const float*)d_in[4];
    const float* W3   = (const float*)d_in[5];
    const float* b3   = (const float*)d_in[6];
    float* y = (float*)d_out;

    cudaFuncSetAttribute(ode_persistent_kernel,
                         cudaFuncAttributeMaxDynamicSharedMemorySize, SMEM_TOTAL);
    ode_init_kernel<<<1, 32>>>();
    ode_persistent_kernel<<<NBLK, TPB, SMEM_TOTAL>>>(y_in, W1, b1, W2, b2, W3, b3, y);
}